// round 5
// baseline (speedup 1.0000x reference)
#include <cuda_runtime.h>
#include <cuda_bf16.h>
#include <cstdint>
#include <math.h>

#define T_TOK 8192
#define DM 1024
#define DF 4096
#define NE 8
#define NSLOT (T_TOK * 2)

// ---------------- device scratch (no allocations allowed) ----------------
__device__ float g_h[(size_t)NSLOT * DF];      // gelu(x@W1+b1), tf32-rounded
__device__ float g_y[(size_t)NSLOT * DM];      // h@W2+b2
__device__ float g_xr[(size_t)T_TOK * DM];     // tf32-rounded x
__device__ float g_W1r[(size_t)NE * DM * DF];  // tf32-rounded W1 (same layout)
__device__ float g_W2r[(size_t)NE * DF * DM];  // tf32-rounded W2 (same layout)
__device__ int   g_slot_tok[NSLOT];
__device__ int   g_tok_slot[NSLOT];
__device__ float g_tok_w[NSLOT];
__device__ int   g_tok_e[NSLOT];
__device__ int   g_cnt[NE];
__device__ int   g_cursor[NE];
__device__ int   g_off[NE];

// ---------------- helpers ----------------
__device__ __forceinline__ unsigned f2tf32(float f) {
    unsigned u;
    asm("cvt.rna.tf32.f32 %0, %1;" : "=r"(u) : "f"(f));
    return u;
}
__device__ __forceinline__ float rna_tf32(float f) { return __uint_as_float(f2tf32(f)); }

__device__ __forceinline__ void mma_tf32(float c[4], unsigned a0, unsigned a1,
                                         unsigned a2, unsigned a3,
                                         unsigned b0, unsigned b1) {
    asm volatile(
        "mma.sync.aligned.m16n8k8.row.col.f32.tf32.tf32.f32 "
        "{%0,%1,%2,%3},{%4,%5,%6,%7},{%8,%9},{%0,%1,%2,%3};\n"
        : "+f"(c[0]), "+f"(c[1]), "+f"(c[2]), "+f"(c[3])
        : "r"(a0), "r"(a1), "r"(a2), "r"(a3), "r"(b0), "r"(b1));
}

__device__ __forceinline__ void cp_async16(unsigned smem_addr, const void* gptr, int src_bytes) {
    asm volatile("cp.async.ca.shared.global [%0], [%1], 16, %2;\n"
                 :: "r"(smem_addr), "l"(gptr), "r"(src_bytes));
}
__device__ __forceinline__ void cp_commit() { asm volatile("cp.async.commit_group;\n"); }
__device__ __forceinline__ void cp_wait0()  { asm volatile("cp.async.wait_group 0;\n"); }

__device__ __forceinline__ float gelu_exact(float c) {
    return 0.5f * c * (1.0f + erff(c * 0.70710678118654752f));
}

// ---------------- tiny bookkeeping kernels ----------------
__global__ void init_kernel() {
    int i = threadIdx.x;
    if (i < NE) { g_cnt[i] = 0; g_cursor[i] = 0; }
}

__global__ void router_kernel(const float* __restrict__ x,
                              const float* __restrict__ Wr,
                              const float* __restrict__ br) {
    int warp = threadIdx.x >> 5;
    int lane = threadIdx.x & 31;
    int t = blockIdx.x * (blockDim.x >> 5) + warp;
    if (t >= T_TOK) return;
    const float* xr = x + (size_t)t * DM;
    float acc[NE];
#pragma unroll
    for (int e = 0; e < NE; e++) acc[e] = 0.f;
    for (int d = lane; d < DM; d += 32) {
        float xv = xr[d];
        const float* w = Wr + (size_t)d * NE;
#pragma unroll
        for (int e = 0; e < NE; e++) acc[e] += xv * w[e];
    }
#pragma unroll
    for (int off = 16; off > 0; off >>= 1) {
#pragma unroll
        for (int e = 0; e < NE; e++)
            acc[e] += __shfl_xor_sync(0xffffffffu, acc[e], off);
    }
    if (lane == 0) {
        float l[NE];
#pragma unroll
        for (int e = 0; e < NE; e++) l[e] = acc[e] + br[e];
        int e0 = 0;
#pragma unroll
        for (int e = 1; e < NE; e++) if (l[e] > l[e0]) e0 = e;
        int e1 = (e0 == 0) ? 1 : 0;
#pragma unroll
        for (int e = 0; e < NE; e++) if (e != e0 && l[e] > l[e1]) e1 = e;
        float w0 = 1.f / (1.f + expf(l[e1] - l[e0]));
        float w1 = 1.f / (1.f + expf(l[e0] - l[e1]));
        g_tok_e[2 * t]     = e0;
        g_tok_e[2 * t + 1] = e1;
        g_tok_w[2 * t]     = w0;
        g_tok_w[2 * t + 1] = w1;
        atomicAdd(&g_cnt[e0], 1);
        atomicAdd(&g_cnt[e1], 1);
    }
}

__global__ void offsets_kernel() {
    int o = 0;
    for (int e = 0; e < NE; e++) { g_off[e] = o; o += g_cnt[e]; }
}

__global__ void assign_kernel() {
    int t = blockIdx.x * blockDim.x + threadIdx.x;
    if (t >= T_TOK) return;
#pragma unroll
    for (int k = 0; k < 2; k++) {
        int e = g_tok_e[2 * t + k];
        int pos = atomicAdd(&g_cursor[e], 1);
        int slot = g_off[e] + pos;
        g_slot_tok[slot] = t;
        g_tok_slot[2 * t + k] = slot;
    }
}

// ---------------- prep: tf32-rna round arrays (float4 vectorized) ----------------
__global__ void round_arr_kernel(const float* __restrict__ src, float* __restrict__ dst) {
    size_t i = ((size_t)blockIdx.x * blockDim.x + threadIdx.x) * 4;
    float4 v = *(const float4*)(src + i);
    v.x = rna_tf32(v.x); v.y = rna_tf32(v.y); v.z = rna_tf32(v.z); v.w = rna_tf32(v.w);
    *(float4*)(dst + i) = v;
}

// =====================================================================
// Tensor-core GEMM (tf32 mma.sync m16n8k8), pre-rounded operands (no
// in-loop CVT: raw fp32 bit patterns with dead low mantissa bits).
// Block tile 128(M) x 256(N) x 8(K), 256 threads = 8 warps (2x4),
// warp tile 64x64 = 4x8 mma tiles. Double-buffered cp.async smem.
//   sA stride 12  -> frag banks (12g + t) mod 32 all distinct
//   sB stride 264 -> frag banks (8t + g)  mod 32 all distinct
// =====================================================================

#define SA_STR 12
#define SB_STR 264

template <int KDIM, bool GATHER, bool DO_GELU>
__global__ __launch_bounds__(256, 1) void gemm_tc_kernel(
    const float* __restrict__ Asrc,     // GATHER: g_xr ; else: g_h
    const float* __restrict__ W,        // [E][KDIM][NDIM] (pre-rounded)
    const float* __restrict__ bias,     // [E][NDIM]
    float* __restrict__ Out,            // g_h or g_y
    int NDIM)
{
    const int e   = blockIdx.z;
    const int cnt = g_cnt[e];
    const int m0  = blockIdx.x * 128;
    if (m0 >= cnt) return;
    const int off = g_off[e];
    const int n0  = blockIdx.y * 256;
    const float* B = W + (size_t)e * KDIM * NDIM;

    __shared__ float sA[2][128][SA_STR];
    __shared__ float sB[2][8][SB_STR];
    __shared__ int s_tok[128];

    const int tid  = threadIdx.x;
    const int wid  = tid >> 5;
    const int lane = tid & 31;
    const int wm   = (wid >> 2) * 64;   // warp m offset (0 or 64)
    const int wn   = (wid & 3) * 64;    // warp n offset
    const int g    = lane >> 2;
    const int t    = lane & 3;

    if (GATHER) {
        if (tid < 128) {
            int m = m0 + tid;
            s_tok[tid] = (m < cnt) ? g_slot_tok[off + m] : -1;
        }
        __syncthreads();
    }

    // ---- A loader: one float4 per thread per iter ----
    const int arow = tid >> 1;
    const int acol = (tid & 1) * 4;
    const float* a_src;
    int a_sz;
    if (GATHER) {
        int tok = s_tok[arow];
        a_sz  = (tok >= 0) ? 16 : 0;
        a_src = Asrc + (size_t)(tok >= 0 ? tok : 0) * KDIM + acol;
    } else {
        int m = m0 + arow;
        a_sz  = (m < cnt) ? 16 : 0;
        a_src = Asrc + (size_t)(off + (m < cnt ? m : 0)) * KDIM + acol;
    }
    // ---- B loader: two float4 per thread per iter ----
    const int brow  = tid >> 5;
    const int bcol  = (tid & 31) * 4;
    const float* b_src = B + (size_t)brow * NDIM + n0 + bcol;

    unsigned sa_addr[2], sb_addr0[2], sb_addr1[2];
#pragma unroll
    for (int bf = 0; bf < 2; bf++) {
        sa_addr[bf]  = (unsigned)__cvta_generic_to_shared(&sA[bf][arow][acol]);
        sb_addr0[bf] = (unsigned)__cvta_generic_to_shared(&sB[bf][brow][bcol]);
        sb_addr1[bf] = (unsigned)__cvta_generic_to_shared(&sB[bf][brow][bcol + 128]);
    }

    float acc[4][8][4];
#pragma unroll
    for (int mi = 0; mi < 4; mi++)
#pragma unroll
        for (int ni = 0; ni < 8; ni++)
#pragma unroll
            for (int r = 0; r < 4; r++) acc[mi][ni][r] = 0.f;

    const int NK = KDIM / 8;

    // prefetch iter 0 into buffer 0
    cp_async16(sa_addr[0], a_src, a_sz);
    cp_async16(sb_addr0[0], b_src, 16);
    cp_async16(sb_addr1[0], b_src + 128, 16);
    cp_commit();

    int buf = 0;
    for (int kt = 0; kt < NK; kt++) {
        cp_wait0();
        __syncthreads();
        if (kt + 1 < NK) {
            const int k0 = (kt + 1) * 8;
            cp_async16(sa_addr[buf ^ 1], a_src + k0, a_sz);
            cp_async16(sb_addr0[buf ^ 1], b_src + (size_t)k0 * NDIM, 16);
            cp_async16(sb_addr1[buf ^ 1], b_src + (size_t)k0 * NDIM + 128, 16);
            cp_commit();
        }

        // ---- fragments: raw bit loads, no CVT (operands pre-rounded) ----
        unsigned afr[4][4];
#pragma unroll
        for (int mi = 0; mi < 4; mi++) {
            const int rm = wm + mi * 16 + g;
            afr[mi][0] = __float_as_uint(sA[buf][rm][t]);
            afr[mi][1] = __float_as_uint(sA[buf][rm + 8][t]);
            afr[mi][2] = __float_as_uint(sA[buf][rm][t + 4]);
            afr[mi][3] = __float_as_uint(sA[buf][rm + 8][t + 4]);
        }
        unsigned bfr[8][2];
#pragma unroll
        for (int ni = 0; ni < 8; ni++) {
            const int cn = wn + ni * 8 + g;
            bfr[ni][0] = __float_as_uint(sB[buf][t][cn]);
            bfr[ni][1] = __float_as_uint(sB[buf][t + 4][cn]);
        }
#pragma unroll
        for (int mi = 0; mi < 4; mi++)
#pragma unroll
            for (int ni = 0; ni < 8; ni++)
                mma_tf32(acc[mi][ni], afr[mi][0], afr[mi][1], afr[mi][2], afr[mi][3],
                         bfr[ni][0], bfr[ni][1]);
        buf ^= 1;
    }

    // ---- epilogue: bias (+ gelu, rounded for next GEMM) + store ----
    const float* be = bias + (size_t)e * NDIM;
#pragma unroll
    for (int ni = 0; ni < 8; ni++) {
        const int cn = n0 + wn + ni * 8 + 2 * t;
        const float2 bv = *(const float2*)(be + cn);
#pragma unroll
        for (int mi = 0; mi < 4; mi++) {
            const int mrow = m0 + wm + mi * 16 + g;
            if (mrow < cnt) {
                float v0 = acc[mi][ni][0] + bv.x;
                float v1 = acc[mi][ni][1] + bv.y;
                if (DO_GELU) { v0 = rna_tf32(gelu_exact(v0)); v1 = rna_tf32(gelu_exact(v1)); }
                *(float2*)(Out + (size_t)(off + mrow) * NDIM + cn) = make_float2(v0, v1);
            }
            if (mrow + 8 < cnt) {
                float v2 = acc[mi][ni][2] + bv.x;
                float v3 = acc[mi][ni][3] + bv.y;
                if (DO_GELU) { v2 = rna_tf32(gelu_exact(v2)); v3 = rna_tf32(gelu_exact(v3)); }
                *(float2*)(Out + (size_t)(off + mrow + 8) * NDIM + cn) = make_float2(v2, v3);
            }
        }
    }
}

// ---------------- combine: out[t] = w0*y[s0] + w1*y[s1] ----------------
__global__ void combine_kernel(float* __restrict__ out) {
    int t = blockIdx.x;
    int d = threadIdx.x * 4;
    int s0 = g_tok_slot[2 * t];
    int s1 = g_tok_slot[2 * t + 1];
    float w0 = g_tok_w[2 * t];
    float w1 = g_tok_w[2 * t + 1];
    float4 y0 = *(const float4*)(g_y + (size_t)s0 * DM + d);
    float4 y1 = *(const float4*)(g_y + (size_t)s1 * DM + d);
    float4 o;
    o.x = w0 * y0.x + w1 * y1.x;
    o.y = w0 * y0.y + w1 * y1.y;
    o.z = w0 * y0.z + w1 * y1.z;
    o.w = w0 * y0.w + w1 * y1.w;
    *(float4*)(out + (size_t)t * DM + d) = o;
}

// ---------------- launch ----------------
extern "C" void kernel_launch(void* const* d_in, const int* in_sizes, int n_in,
                              void* d_out, int out_size) {
    const float* x  = (const float*)d_in[0];
    const float* Wr = (const float*)d_in[1];
    const float* br = (const float*)d_in[2];
    const float* W1 = (const float*)d_in[3];
    const float* b1 = (const float*)d_in[4];
    const float* W2 = (const float*)d_in[5];
    const float* b2 = (const float*)d_in[6];
    float* out = (float*)d_out;

    float* g_h_ptr;   cudaGetSymbolAddress((void**)&g_h_ptr, g_h);
    float* g_y_ptr;   cudaGetSymbolAddress((void**)&g_y_ptr, g_y);
    float* g_xr_ptr;  cudaGetSymbolAddress((void**)&g_xr_ptr, g_xr);
    float* g_W1r_ptr; cudaGetSymbolAddress((void**)&g_W1r_ptr, g_W1r);
    float* g_W2r_ptr; cudaGetSymbolAddress((void**)&g_W2r_ptr, g_W2r);

    init_kernel<<<1, 32>>>();
    router_kernel<<<T_TOK / 8, 256>>>(x, Wr, br);
    offsets_kernel<<<1, 1>>>();
    assign_kernel<<<T_TOK / 256, 256>>>();

    round_arr_kernel<<<(T_TOK * (size_t)DM / 4) / 256, 256>>>(x, g_xr_ptr);
    round_arr_kernel<<<((size_t)NE * DM * DF / 4) / 256, 256>>>(W1, g_W1r_ptr);
    round_arr_kernel<<<((size_t)NE * DF * DM / 4) / 256, 256>>>(W2, g_W2r_ptr);

    dim3 g1(T_TOK / 128, DF / 256, NE);
    gemm_tc_kernel<DM, true, true><<<g1, 256>>>(g_xr_ptr, g_W1r_ptr, b1, g_h_ptr, DF);

    dim3 g2(T_TOK / 128, DM / 256, NE);
    gemm_tc_kernel<DF, false, false><<<g2, 256>>>(g_h_ptr, g_W2r_ptr, b2, g_y_ptr, DM);

    combine_kernel<<<T_TOK, 256>>>(out);
}

// round 6
// speedup vs baseline: 1.3222x; 1.3222x over previous
#include <cuda_runtime.h>
#include <cuda_bf16.h>
#include <cstdint>
#include <math.h>

#define T_TOK 8192
#define DM 1024
#define DF 4096
#define NE 8
#define NSLOT (T_TOK * 2)

// ---------------- device scratch (no allocations allowed) ----------------
__device__ float g_h[(size_t)NSLOT * DF];      // gelu(x@W1+b1), tf32-rounded
__device__ float g_y[(size_t)NSLOT * DM];      // h@W2+b2
__device__ float g_xr[(size_t)T_TOK * DM];     // tf32-rounded x
__device__ float g_W1r[(size_t)NE * DM * DF];  // tf32-rounded W1 (same layout)
__device__ float g_W2r[(size_t)NE * DF * DM];  // tf32-rounded W2 (same layout)
__device__ int   g_slot_tok[NSLOT];
__device__ int   g_tok_slot[NSLOT];
__device__ float g_tok_w[NSLOT];
__device__ int   g_tok_e[NSLOT];
__device__ int   g_cnt[NE];
__device__ int   g_cursor[NE];
__device__ int   g_off[NE];

// ---------------- helpers ----------------
__device__ __forceinline__ unsigned f2tf32(float f) {
    unsigned u;
    asm("cvt.rna.tf32.f32 %0, %1;" : "=r"(u) : "f"(f));
    return u;
}
__device__ __forceinline__ float rna_tf32(float f) { return __uint_as_float(f2tf32(f)); }

__device__ __forceinline__ void mma_tf32(float c[4], unsigned a0, unsigned a1,
                                         unsigned a2, unsigned a3,
                                         unsigned b0, unsigned b1) {
    asm volatile(
        "mma.sync.aligned.m16n8k8.row.col.f32.tf32.tf32.f32 "
        "{%0,%1,%2,%3},{%4,%5,%6,%7},{%8,%9},{%0,%1,%2,%3};\n"
        : "+f"(c[0]), "+f"(c[1]), "+f"(c[2]), "+f"(c[3])
        : "r"(a0), "r"(a1), "r"(a2), "r"(a3), "r"(b0), "r"(b1));
}

__device__ __forceinline__ void cp_async16(unsigned smem_addr, const void* gptr, int src_bytes) {
    asm volatile("cp.async.ca.shared.global [%0], [%1], 16, %2;\n"
                 :: "r"(smem_addr), "l"(gptr), "r"(src_bytes));
}
__device__ __forceinline__ void cp_commit() { asm volatile("cp.async.commit_group;\n"); }
template <int N>
__device__ __forceinline__ void cp_wait() { asm volatile("cp.async.wait_group %0;\n" :: "n"(N)); }

__device__ __forceinline__ float gelu_exact(float c) {
    return 0.5f * c * (1.0f + erff(c * 0.70710678118654752f));
}

// ---------------- tiny bookkeeping kernels ----------------
__global__ void init_kernel() {
    int i = threadIdx.x;
    if (i < NE) { g_cnt[i] = 0; g_cursor[i] = 0; }
}

__global__ void router_kernel(const float* __restrict__ x,
                              const float* __restrict__ Wr,
                              const float* __restrict__ br) {
    int warp = threadIdx.x >> 5;
    int lane = threadIdx.x & 31;
    int t = blockIdx.x * (blockDim.x >> 5) + warp;
    if (t >= T_TOK) return;
    const float* xr = x + (size_t)t * DM;
    float acc[NE];
#pragma unroll
    for (int e = 0; e < NE; e++) acc[e] = 0.f;
    for (int d = lane; d < DM; d += 32) {
        float xv = xr[d];
        const float* w = Wr + (size_t)d * NE;
#pragma unroll
        for (int e = 0; e < NE; e++) acc[e] += xv * w[e];
    }
#pragma unroll
    for (int off = 16; off > 0; off >>= 1) {
#pragma unroll
        for (int e = 0; e < NE; e++)
            acc[e] += __shfl_xor_sync(0xffffffffu, acc[e], off);
    }
    if (lane == 0) {
        float l[NE];
#pragma unroll
        for (int e = 0; e < NE; e++) l[e] = acc[e] + br[e];
        int e0 = 0;
#pragma unroll
        for (int e = 1; e < NE; e++) if (l[e] > l[e0]) e0 = e;
        int e1 = (e0 == 0) ? 1 : 0;
#pragma unroll
        for (int e = 0; e < NE; e++) if (e != e0 && l[e] > l[e1]) e1 = e;
        float w0 = 1.f / (1.f + expf(l[e1] - l[e0]));
        float w1 = 1.f / (1.f + expf(l[e0] - l[e1]));
        g_tok_e[2 * t]     = e0;
        g_tok_e[2 * t + 1] = e1;
        g_tok_w[2 * t]     = w0;
        g_tok_w[2 * t + 1] = w1;
        atomicAdd(&g_cnt[e0], 1);
        atomicAdd(&g_cnt[e1], 1);
    }
}

__global__ void offsets_kernel() {
    int o = 0;
    for (int e = 0; e < NE; e++) { g_off[e] = o; o += g_cnt[e]; }
}

__global__ void assign_kernel() {
    int t = blockIdx.x * blockDim.x + threadIdx.x;
    if (t >= T_TOK) return;
#pragma unroll
    for (int k = 0; k < 2; k++) {
        int e = g_tok_e[2 * t + k];
        int pos = atomicAdd(&g_cursor[e], 1);
        int slot = g_off[e] + pos;
        g_slot_tok[slot] = t;
        g_tok_slot[2 * t + k] = slot;
    }
}

// ---------------- prep: tf32-rna round arrays (float4 vectorized) ----------------
__global__ void round_arr_kernel(const float* __restrict__ src, float* __restrict__ dst) {
    size_t i = ((size_t)blockIdx.x * blockDim.x + threadIdx.x) * 4;
    float4 v = *(const float4*)(src + i);
    v.x = rna_tf32(v.x); v.y = rna_tf32(v.y); v.z = rna_tf32(v.z); v.w = rna_tf32(v.w);
    *(float4*)(dst + i) = v;
}

// =====================================================================
// Tensor-core GEMM (tf32 mma.sync m16n8k8), pre-rounded operands,
// 5-stage cp.async pipeline (wait_group 3) to hide global-load latency.
// Block tile 128(M) x 256(N) x 8(K), 256 threads = 8 warps (2x4),
// warp tile 64x64 = 4x8 mma tiles.
//   sA stage: [128][12] (stride 12 -> frag banks (12g+t)%32 distinct)
//   sB stage: [8][264]  (stride 264 -> frag banks (8t+g)%32 distinct)
// =====================================================================

#define STAGES 5
#define SA_STR 12
#define SB_STR 264
#define A_STG_F (128 * SA_STR)           // 1536 floats
#define B_STG_F (8 * SB_STR)             // 2112 floats
#define SMEM_DYN ((STAGES * (A_STG_F + B_STG_F)) * 4)   // 72960 B

template <int KDIM, bool GATHER, bool DO_GELU>
__global__ __launch_bounds__(256, 1) void gemm_tc_kernel(
    const float* __restrict__ Asrc,     // GATHER: g_xr ; else: g_h
    const float* __restrict__ W,        // [E][KDIM][NDIM] (pre-rounded)
    const float* __restrict__ bias,     // [E][NDIM]
    float* __restrict__ Out,            // g_h or g_y
    int NDIM)
{
    const int e   = blockIdx.z;
    const int cnt = g_cnt[e];
    const int m0  = blockIdx.x * 128;
    if (m0 >= cnt) return;
    const int off = g_off[e];
    const int n0  = blockIdx.y * 256;
    const float* B = W + (size_t)e * KDIM * NDIM;

    extern __shared__ float dsm[];
    float* sAb = dsm;                       // [STAGES][128][SA_STR]
    float* sBb = dsm + STAGES * A_STG_F;    // [STAGES][8][SB_STR]
    __shared__ int s_tok[128];

    const int tid  = threadIdx.x;
    const int wid  = tid >> 5;
    const int lane = tid & 31;
    const int wm   = (wid >> 2) * 64;   // warp m offset (0 or 64)
    const int wn   = (wid & 3) * 64;    // warp n offset
    const int g    = lane >> 2;
    const int t    = lane & 3;

    if (GATHER) {
        if (tid < 128) {
            int m = m0 + tid;
            s_tok[tid] = (m < cnt) ? g_slot_tok[off + m] : -1;
        }
        __syncthreads();
    }

    // ---- A loader: one float4 per thread per stage ----
    const int arow = tid >> 1;
    const int acol = (tid & 1) * 4;
    const float* a_src;
    int a_sz;
    if (GATHER) {
        int tok = s_tok[arow];
        a_sz  = (tok >= 0) ? 16 : 0;
        a_src = Asrc + (size_t)(tok >= 0 ? tok : 0) * KDIM + acol;
    } else {
        int m = m0 + arow;
        a_sz  = (m < cnt) ? 16 : 0;
        a_src = Asrc + (size_t)(off + (m < cnt ? m : 0)) * KDIM + acol;
    }
    // ---- B loader: two float4 per thread per stage ----
    const int brow  = tid >> 5;
    const int bcol  = (tid & 31) * 4;
    const float* b_src = B + (size_t)brow * NDIM + n0 + bcol;

    const unsigned saBase = (unsigned)__cvta_generic_to_shared(sAb)
                          + (unsigned)(arow * SA_STR + acol) * 4u;
    const unsigned sbBase = (unsigned)__cvta_generic_to_shared(sBb)
                          + (unsigned)(brow * SB_STR + bcol) * 4u;

    const int NK = KDIM / 8;

    auto load_stage = [&](int s) {
        if (s < NK) {
            const int buf = s % STAGES;
            const int k0 = s * 8;
            cp_async16(saBase + (unsigned)(buf * A_STG_F) * 4u, a_src + k0, a_sz);
            cp_async16(sbBase + (unsigned)(buf * B_STG_F) * 4u,
                       b_src + (size_t)k0 * NDIM, 16);
            cp_async16(sbBase + (unsigned)(buf * B_STG_F) * 4u + 512u,
                       b_src + (size_t)k0 * NDIM + 128, 16);
        }
        cp_commit();
    };

    float acc[4][8][4];
#pragma unroll
    for (int mi = 0; mi < 4; mi++)
#pragma unroll
        for (int ni = 0; ni < 8; ni++)
#pragma unroll
            for (int r = 0; r < 4; r++) acc[mi][ni][r] = 0.f;

    // prologue: prefetch stages 0..STAGES-2
#pragma unroll
    for (int s = 0; s < STAGES - 1; s++) load_stage(s);

    for (int kt = 0; kt < NK; kt++) {
        cp_wait<STAGES - 2>();
        __syncthreads();
        load_stage(kt + STAGES - 1);   // one commit per iter keeps group math exact

        const int buf = kt % STAGES;
        const float* sA = sAb + buf * A_STG_F;
        const float* sB = sBb + buf * B_STG_F;

        unsigned afr[4][4];
#pragma unroll
        for (int mi = 0; mi < 4; mi++) {
            const int rm = wm + mi * 16 + g;
            afr[mi][0] = __float_as_uint(sA[rm * SA_STR + t]);
            afr[mi][1] = __float_as_uint(sA[(rm + 8) * SA_STR + t]);
            afr[mi][2] = __float_as_uint(sA[rm * SA_STR + t + 4]);
            afr[mi][3] = __float_as_uint(sA[(rm + 8) * SA_STR + t + 4]);
        }
        unsigned bfr[8][2];
#pragma unroll
        for (int ni = 0; ni < 8; ni++) {
            const int cn = wn + ni * 8 + g;
            bfr[ni][0] = __float_as_uint(sB[t * SB_STR + cn]);
            bfr[ni][1] = __float_as_uint(sB[(t + 4) * SB_STR + cn]);
        }
#pragma unroll
        for (int mi = 0; mi < 4; mi++)
#pragma unroll
            for (int ni = 0; ni < 8; ni++)
                mma_tf32(acc[mi][ni], afr[mi][0], afr[mi][1], afr[mi][2], afr[mi][3],
                         bfr[ni][0], bfr[ni][1]);
    }

    // ---- epilogue: bias (+ gelu, rounded for next GEMM) + store ----
    const float* be = bias + (size_t)e * NDIM;
#pragma unroll
    for (int ni = 0; ni < 8; ni++) {
        const int cn = n0 + wn + ni * 8 + 2 * t;
        const float2 bv = *(const float2*)(be + cn);
#pragma unroll
        for (int mi = 0; mi < 4; mi++) {
            const int mrow = m0 + wm + mi * 16 + g;
            if (mrow < cnt) {
                float v0 = acc[mi][ni][0] + bv.x;
                float v1 = acc[mi][ni][1] + bv.y;
                if (DO_GELU) { v0 = rna_tf32(gelu_exact(v0)); v1 = rna_tf32(gelu_exact(v1)); }
                *(float2*)(Out + (size_t)(off + mrow) * NDIM + cn) = make_float2(v0, v1);
            }
            if (mrow + 8 < cnt) {
                float v2 = acc[mi][ni][2] + bv.x;
                float v3 = acc[mi][ni][3] + bv.y;
                if (DO_GELU) { v2 = rna_tf32(gelu_exact(v2)); v3 = rna_tf32(gelu_exact(v3)); }
                *(float2*)(Out + (size_t)(off + mrow + 8) * NDIM + cn) = make_float2(v2, v3);
            }
        }
    }
}

// ---------------- combine: out[t] = w0*y[s0] + w1*y[s1] ----------------
__global__ void combine_kernel(float* __restrict__ out) {
    int t = blockIdx.x;
    int d = threadIdx.x * 4;
    int s0 = g_tok_slot[2 * t];
    int s1 = g_tok_slot[2 * t + 1];
    float w0 = g_tok_w[2 * t];
    float w1 = g_tok_w[2 * t + 1];
    float4 y0 = *(const float4*)(g_y + (size_t)s0 * DM + d);
    float4 y1 = *(const float4*)(g_y + (size_t)s1 * DM + d);
    float4 o;
    o.x = w0 * y0.x + w1 * y1.x;
    o.y = w0 * y0.y + w1 * y1.y;
    o.z = w0 * y0.z + w1 * y1.z;
    o.w = w0 * y0.w + w1 * y1.w;
    *(float4*)(out + (size_t)t * DM + d) = o;
}

// ---------------- launch ----------------
extern "C" void kernel_launch(void* const* d_in, const int* in_sizes, int n_in,
                              void* d_out, int out_size) {
    const float* x  = (const float*)d_in[0];
    const float* Wr = (const float*)d_in[1];
    const float* br = (const float*)d_in[2];
    const float* W1 = (const float*)d_in[3];
    const float* b1 = (const float*)d_in[4];
    const float* W2 = (const float*)d_in[5];
    const float* b2 = (const float*)d_in[6];
    float* out = (float*)d_out;

    cudaFuncSetAttribute(gemm_tc_kernel<DM, true, true>,
                         cudaFuncAttributeMaxDynamicSharedMemorySize, SMEM_DYN);
    cudaFuncSetAttribute(gemm_tc_kernel<DF, false, false>,
                         cudaFuncAttributeMaxDynamicSharedMemorySize, SMEM_DYN);

    float* g_h_ptr;   cudaGetSymbolAddress((void**)&g_h_ptr, g_h);
    float* g_y_ptr;   cudaGetSymbolAddress((void**)&g_y_ptr, g_y);
    float* g_xr_ptr;  cudaGetSymbolAddress((void**)&g_xr_ptr, g_xr);
    float* g_W1r_ptr; cudaGetSymbolAddress((void**)&g_W1r_ptr, g_W1r);
    float* g_W2r_ptr; cudaGetSymbolAddress((void**)&g_W2r_ptr, g_W2r);

    init_kernel<<<1, 32>>>();
    router_kernel<<<T_TOK / 8, 256>>>(x, Wr, br);
    offsets_kernel<<<1, 1>>>();
    assign_kernel<<<T_TOK / 256, 256>>>();

    round_arr_kernel<<<(T_TOK * (size_t)DM / 4) / 256, 256>>>(x, g_xr_ptr);
    round_arr_kernel<<<((size_t)NE * DM * DF / 4) / 256, 256>>>(W1, g_W1r_ptr);
    round_arr_kernel<<<((size_t)NE * DF * DM / 4) / 256, 256>>>(W2, g_W2r_ptr);

    dim3 g1(T_TOK / 128, DF / 256, NE);
    gemm_tc_kernel<DM, true, true><<<g1, 256, SMEM_DYN>>>(g_xr_ptr, g_W1r_ptr, b1, g_h_ptr, DF);

    dim3 g2(T_TOK / 128, DM / 256, NE);
    gemm_tc_kernel<DF, false, false><<<g2, 256, SMEM_DYN>>>(g_h_ptr, g_W2r_ptr, b2, g_y_ptr, DM);

    combine_kernel<<<T_TOK, 256>>>(out);
}